// round 14
// baseline (speedup 1.0000x reference)
#include <cuda_runtime.h>
#include <cstdint>

#define N_NODESC 100000
#define N_EDGESC 625000
#define DIM 128
#define BN_EPS 1e-5f

#define SCAN_B 512
#define NBLK ((N_NODESC + SCAN_B - 1) / SCAN_B)   // 196

#define ROWS_PER_WARP 8
#define NGROUPS8 (N_NODESC / ROWS_PER_WARP)        // 12500 exactly
#define NTASKS (2 * NGROUPS8)                      // (group, matrix) pairs
#define GEMM_GRID 444                              // 3552 warps (even => parity-stable)

// ---------------- scratch (static device globals; no allocs) ----------------
__device__ __align__(16) float g_deg[N_NODESC];
__device__ int   g_cnt[N_NODESC];
__device__ int   g_rowptr[N_NODESC + 1];
__device__ int   g_cursor[N_NODESC];
__device__ int   g_bsum[NBLK];
__device__ int   g_src[N_EDGESC];
__device__ __align__(16) float g_nrm[N_EDGESC];
__device__ __align__(16) float g_hg[N_NODESC * DIM];
__device__ __align__(16) float g_acc[N_NODESC * DIM];
__device__ __align__(16) float g_xbuf[N_NODESC * DIM];
__device__ __align__(16) float g_WT[2 * 2 * DIM * DIM];   // [layer][branch][k][j]
__device__ __align__(16) float g_stats[2 * 2 * DIM];      // [layer][sum|sumsq][d]
__device__ int g_is64;

// ---------------- packed f32x2 helpers (Blackwell sm_100+) ----------------
__device__ __forceinline__ unsigned long long pack_dup(float c) {
    unsigned long long r;
    asm("mov.b64 %0, {%1, %1};" : "=l"(r) : "f"(c));
    return r;
}
__device__ __forceinline__ void fma2(unsigned long long& acc, unsigned long long ab,
                                     unsigned long long w) {
    asm("fma.rn.f32x2 %0, %1, %2, %0;" : "+l"(acc) : "l"(ab), "l"(w));
}

// ---------------- dtype probe: int64 arrays have zero high-words ------------
__global__ void k_probe(const int* __restrict__ ei32) {
    if (threadIdx.x == 0 && blockIdx.x == 0) {
        int allzero = 1;
        for (int i = 1; i < 16; i += 2)
            if (ei32[i] != 0) allzero = 0;
        g_is64 = allzero;
    }
}
__device__ __forceinline__ int load_row(const int* ei32, int e, int is64) {
    return is64 ? ei32[2 * e] : ei32[e];
}
__device__ __forceinline__ int load_col(const int* ei32, int e, int is64) {
    return is64 ? ei32[2 * (N_EDGESC + e)] : ei32[N_EDGESC + e];
}

// ---------------- setup kernels ----------------
__global__ void k_zero() {
    int i = blockIdx.x * blockDim.x + threadIdx.x;
    if (i < N_NODESC) { g_deg[i] = 0.f; g_cnt[i] = 0; }
    if (i < 2 * 2 * DIM) g_stats[i] = 0.f;
}

__global__ void k_deg(const int* __restrict__ ei32, const float* __restrict__ ew) {
    int e = blockIdx.x * blockDim.x + threadIdx.x;
    if (e < N_EDGESC) {
        int is64 = g_is64;
        int c = load_col(ei32, e, is64);
        atomicAdd(&g_deg[c], ew[e]);
        atomicAdd(&g_cnt[c], 1);
    }
}

__global__ void k_scan1() {
    __shared__ int s[SCAN_B];
    int tid = threadIdx.x;
    int i = blockIdx.x * SCAN_B + tid;
    s[tid] = (i < N_NODESC) ? g_cnt[i] : 0;
    __syncthreads();
    for (int off = SCAN_B / 2; off > 0; off >>= 1) {
        if (tid < off) s[tid] += s[tid + off];
        __syncthreads();
    }
    if (tid == 0) g_bsum[blockIdx.x] = s[0];
}

__global__ void k_scan2() {
    if (threadIdx.x == 0) {
        int run = 0;
        for (int b = 0; b < NBLK; b++) { int t = g_bsum[b]; g_bsum[b] = run; run += t; }
        g_rowptr[N_NODESC] = run;
    }
}

__global__ void k_scan3() {
    __shared__ int s[SCAN_B];
    int tid = threadIdx.x;
    int i = blockIdx.x * SCAN_B + tid;
    int v = (i < N_NODESC) ? g_cnt[i] : 0;
    s[tid] = v;
    __syncthreads();
    for (int off = 1; off < SCAN_B; off <<= 1) {
        int t = (tid >= off) ? s[tid - off] : 0;
        __syncthreads();
        s[tid] += t;
        __syncthreads();
    }
    if (i < N_NODESC) {
        int excl = g_bsum[blockIdx.x] + s[tid] - v;
        g_rowptr[i] = excl;
        g_cursor[i] = excl;
    }
}

__global__ void k_edges(const int* __restrict__ ei32, const float* __restrict__ ew) {
    int e = blockIdx.x * blockDim.x + threadIdx.x;
    if (e < N_EDGESC) {
        int is64 = g_is64;
        int r = load_row(ei32, e, is64);
        int c = load_col(ei32, e, is64);
        float w = ew[e];
        float dr = g_deg[r], dc = g_deg[c];
        float nv = (dr > 0.f ? rsqrtf(dr) : 0.f) * w * (dc > 0.f ? rsqrtf(dc) : 0.f);
        int pos = atomicAdd(&g_cursor[c], 1);
        g_src[pos] = r;
        g_nrm[pos] = nv;
    }
}

// transpose both weight matrices of both layers:  WT[(ly*2+br)*D + k][j] = W[ly][j][k]
__global__ void k_transW(const float* __restrict__ Wl, const float* __restrict__ Wg) {
    int t = blockIdx.x * blockDim.x + threadIdx.x;
    if (t < 2 * 2 * DIM * DIM) {
        int j  = t & (DIM - 1);
        int k  = (t >> 7) & (DIM - 1);
        int br = (t >> 14) & 1;
        int ly = t >> 15;
        const float* src = br ? Wg : Wl;
        g_WT[t] = src[ly * DIM * DIM + j * DIM + k];
    }
}

// ---------------- GEMM: dstA = src' @ Wl^T, dstH = src' @ Wg^T -------------
// src' = src raw (fused=0) or BN+ReLU(src) with previous layer's stats (fused=1).
// Warp = 8 rows x ONE matrix (parity of warp id picks Wl/Wg); lane owns 4 cols.
// Weights for 4 kk hoisted per-q (16 regs), reused across 8 rows. FFMA2 math.
__global__ void __launch_bounds__(256) k_gemm(
    const float* __restrict__ src, int fused,
    float* __restrict__ dstA, float* __restrict__ dstH,
    const float* __restrict__ gamma, const float* __restrict__ beta, int layer) {
    __shared__ float s_sc[DIM];
    __shared__ float s_sh[DIM];
    if (fused) {
        if (threadIdx.x < DIM) {
            int d = threadIdx.x;
            const float inv_n = 1.f / (float)N_NODESC;
            float mu = g_stats[(layer - 1) * 2 * DIM + d] * inv_n;
            float var = g_stats[(layer - 1) * 2 * DIM + DIM + d] * inv_n - mu * mu;
            float sc = rsqrtf(var + BN_EPS) * gamma[(layer - 1) * DIM + d];
            s_sc[d] = sc;
            s_sh[d] = beta[(layer - 1) * DIM + d] - mu * sc;
        }
        __syncthreads();
    }
    int lane = threadIdx.x & 31;
    int warp = (blockIdx.x * blockDim.x + threadIdx.x) >> 5;
    int nwarps = (gridDim.x * blockDim.x) >> 5;   // even => task parity stable

    const int mat = warp & 1;
    const ulonglong2* W = (const ulonglong2*)(g_WT + (layer * 2 + mat) * DIM * DIM);
    float* dst = mat ? dstH : dstA;

    for (int t = warp; t < NTASKS; t += nwarps) {
        int g = t >> 1;                    // t&1 == mat (parity preserved)
        int n0 = g * ROWS_PER_WARP;
        const float4* x0 = (const float4*)(src + (size_t)n0 * DIM);
        unsigned long long a01[8], a23[8];
#pragma unroll
        for (int r = 0; r < 8; r++) { a01[r] = 0ULL; a23[r] = 0ULL; }

#pragma unroll 2
        for (int q = 0; q < 32; q++) {
            ulonglong2 w0 = W[(4 * q + 0) * 32 + lane];
            ulonglong2 w1 = W[(4 * q + 1) * 32 + lane];
            ulonglong2 w2 = W[(4 * q + 2) * 32 + lane];
            ulonglong2 w3 = W[(4 * q + 3) * 32 + lane];
            float4 sc, sh;
            if (fused) {
                sc = *(const float4*)&s_sc[q * 4];
                sh = *(const float4*)&s_sh[q * 4];
            }
#pragma unroll
            for (int r = 0; r < 8; r++) {
                float4 xv = x0[r * 32 + q];
                if (fused) {
                    xv.x = fmaxf(fmaf(xv.x, sc.x, sh.x), 0.f);
                    xv.y = fmaxf(fmaf(xv.y, sc.y, sh.y), 0.f);
                    xv.z = fmaxf(fmaf(xv.z, sc.z, sh.z), 0.f);
                    xv.w = fmaxf(fmaf(xv.w, sc.w, sh.w), 0.f);
                }
                unsigned long long c0 = pack_dup(xv.x);
                unsigned long long c1 = pack_dup(xv.y);
                unsigned long long c2 = pack_dup(xv.z);
                unsigned long long c3 = pack_dup(xv.w);
                fma2(a01[r], c0, w0.x); fma2(a23[r], c0, w0.y);
                fma2(a01[r], c1, w1.x); fma2(a23[r], c1, w1.y);
                fma2(a01[r], c2, w2.x); fma2(a23[r], c2, w2.y);
                fma2(a01[r], c3, w3.x); fma2(a23[r], c3, w3.y);
            }
        }
#pragma unroll
        for (int r = 0; r < 8; r++) {
            ulonglong2* D = (ulonglong2*)(dst + (size_t)(n0 + r) * DIM);
            D[lane] = make_ulonglong2(a01[r], a23[r]);
        }
    }
}

// ---------------- gather (CSR segment-sum) + BN stats ----------------
__global__ void __launch_bounds__(256) k_gather_bn(int layer, float* __restrict__ accbuf) {
    __shared__ float s_sum[8][DIM];
    __shared__ float s_sq[8][DIM];
    int lane = threadIdx.x & 31;
    int wib = threadIdx.x >> 5;
    int warp = (blockIdx.x * blockDim.x + threadIdx.x) >> 5;
    int nw = (gridDim.x * blockDim.x) >> 5;
    const float4* HG = (const float4*)g_hg;

    float4 sum = make_float4(0.f, 0.f, 0.f, 0.f);
    float4 sq = make_float4(0.f, 0.f, 0.f, 0.f);

    for (int n = warp; n < N_NODESC; n += nw) {
        int start = g_rowptr[n];
        int end = g_rowptr[n + 1];
        float4* A = (float4*)(accbuf + (size_t)n * DIM);
        float4 h = A[lane];
        for (int i = start; i < end; i++) {
            int r = g_src[i];
            float nv = g_nrm[i];
            float4 v = HG[r * 32 + lane];
            h.x = fmaf(nv, v.x, h.x);
            h.y = fmaf(nv, v.y, h.y);
            h.z = fmaf(nv, v.z, h.z);
            h.w = fmaf(nv, v.w, h.w);
        }
        A[lane] = h;
        sum.x += h.x; sum.y += h.y; sum.z += h.z; sum.w += h.w;
        sq.x = fmaf(h.x, h.x, sq.x);
        sq.y = fmaf(h.y, h.y, sq.y);
        sq.z = fmaf(h.z, h.z, sq.z);
        sq.w = fmaf(h.w, h.w, sq.w);
    }
    s_sum[wib][lane * 4 + 0] = sum.x;
    s_sum[wib][lane * 4 + 1] = sum.y;
    s_sum[wib][lane * 4 + 2] = sum.z;
    s_sum[wib][lane * 4 + 3] = sum.w;
    s_sq[wib][lane * 4 + 0] = sq.x;
    s_sq[wib][lane * 4 + 1] = sq.y;
    s_sq[wib][lane * 4 + 2] = sq.z;
    s_sq[wib][lane * 4 + 3] = sq.w;
    __syncthreads();
    if (threadIdx.x < DIM) {
        float ts = 0.f, tq = 0.f;
#pragma unroll
        for (int w = 0; w < 8; w++) { ts += s_sum[w][threadIdx.x]; tq += s_sq[w][threadIdx.x]; }
        atomicAdd(&g_stats[layer * 2 * DIM + threadIdx.x], ts);
        atomicAdd(&g_stats[layer * 2 * DIM + DIM + threadIdx.x], tq);
    }
}

// ---------------- BN apply (final layer, no ReLU) ----------------
__global__ void k_apply(int layer, const float* __restrict__ accbuf,
                        float* __restrict__ outp,
                        const float* __restrict__ gamma, const float* __restrict__ beta) {
    int total = N_NODESC * DIM / 4;
    const float4* A = (const float4*)accbuf;
    float4* O = (float4*)outp;
    const float inv_n = 1.f / (float)N_NODESC;
    for (int i = blockIdx.x * blockDim.x + threadIdx.x; i < total; i += gridDim.x * blockDim.x) {
        int d0 = (i & 31) * 4;
        float4 h = A[i];
        float4 s4 = *(const float4*)&g_stats[layer * 2 * DIM + d0];
        float4 q4 = *(const float4*)&g_stats[layer * 2 * DIM + DIM + d0];
        float4 ga = *(const float4*)&gamma[layer * DIM + d0];
        float4 be = *(const float4*)&beta[layer * DIM + d0];
        float4 o;
        {
            float mu = s4.x * inv_n; float var = q4.x * inv_n - mu * mu;
            o.x = (h.x - mu) * rsqrtf(var + BN_EPS) * ga.x + be.x;
        }
        {
            float mu = s4.y * inv_n; float var = q4.y * inv_n - mu * mu;
            o.y = (h.y - mu) * rsqrtf(var + BN_EPS) * ga.y + be.y;
        }
        {
            float mu = s4.z * inv_n; float var = q4.z * inv_n - mu * mu;
            o.z = (h.z - mu) * rsqrtf(var + BN_EPS) * ga.z + be.z;
        }
        {
            float mu = s4.w * inv_n; float var = q4.w * inv_n - mu * mu;
            o.w = (h.w - mu) * rsqrtf(var + BN_EPS) * ga.w + be.w;
        }
        O[i] = o;
    }
}

// ---------------- launch ----------------
extern "C" void kernel_launch(void* const* d_in, const int* in_sizes, int n_in,
                              void* d_out, int out_size) {
    const float* x = (const float*)d_in[0];
    const int* ei32 = (const int*)d_in[1];
    const float* ew = (const float*)d_in[2];
    const float* Wl = (const float*)d_in[3];
    const float* Wg = (const float*)d_in[4];
    const float* gamma = (const float*)d_in[5];
    const float* beta = (const float*)d_in[6];
    float* out = (float*)d_out;

    float* acc0; cudaGetSymbolAddress((void**)&acc0, g_acc);
    float* acc1; cudaGetSymbolAddress((void**)&acc1, g_xbuf);
    float* hgp;  cudaGetSymbolAddress((void**)&hgp, g_hg);

    // Launch order keeps gemm0 in the ncu capture slot (my index 3).
    k_probe<<<1, 32>>>(ei32);                                        // 0
    k_transW<<<(2 * 2 * DIM * DIM + 255) / 256, 256>>>(Wl, Wg);      // 1
    k_zero<<<(N_NODESC + 255) / 256, 256>>>();                       // 2
    k_gemm<<<GEMM_GRID, 256>>>(x, 0, acc0, hgp, gamma, beta, 0);     // 3  <- profiled
    k_deg<<<(N_EDGESC + 255) / 256, 256>>>(ei32, ew);                // 4
    k_scan1<<<NBLK, SCAN_B>>>();                                     // 5
    k_scan2<<<1, 32>>>();                                            // 6
    k_scan3<<<NBLK, SCAN_B>>>();                                     // 7
    k_edges<<<(N_EDGESC + 255) / 256, 256>>>(ei32, ew);              // 8

    k_gather_bn<<<592, 256>>>(0, acc0);                              // 9
    k_gemm<<<GEMM_GRID, 256>>>(acc0, 1, acc1, hgp, gamma, beta, 1);  // 10
    k_gather_bn<<<592, 256>>>(1, acc1);                              // 11
    k_apply<<<2048, 256>>>(1, acc1, out, gamma, beta);               // 12
}

// round 16
// speedup vs baseline: 1.1120x; 1.1120x over previous
#include <cuda_runtime.h>
#include <cstdint>

#define N_NODESC 100000
#define N_EDGESC 625000
#define DIM 128
#define BN_EPS 1e-5f

#define SCAN_B 512
#define NBLK ((N_NODESC + SCAN_B - 1) / SCAN_B)   // 196

#define ROWS_PER_WARP 4
#define NGROUPS (N_NODESC / ROWS_PER_WARP)         // 25000 exactly
#define GEMM_GRID 592                              // 4 CTAs/SM, one wave

// ---------------- scratch (static device globals; no allocs) ----------------
__device__ __align__(16) float g_deg[N_NODESC];
__device__ int   g_cnt[N_NODESC];
__device__ int   g_rowptr[N_NODESC + 1];
__device__ int   g_cursor[N_NODESC];
__device__ int   g_bsum[NBLK];
__device__ int   g_src[N_EDGESC];
__device__ __align__(16) float g_nrm[N_EDGESC];
__device__ __align__(16) float g_hg[N_NODESC * DIM];
__device__ __align__(16) float g_acc[N_NODESC * DIM];
__device__ __align__(16) float g_xbuf[N_NODESC * DIM];
__device__ __align__(16) float g_WT[2 * 2 * DIM * DIM];   // [layer][branch][k][j]
__device__ __align__(16) float g_stats[2 * 2 * DIM];      // [layer][sum|sumsq][d]
__device__ int g_is64;

// ---------------- packed f32x2 helpers (Blackwell sm_100+) ----------------
__device__ __forceinline__ unsigned long long pack_dup(float c) {
    unsigned long long r;
    asm("mov.b64 %0, {%1, %1};" : "=l"(r) : "f"(c));
    return r;
}
__device__ __forceinline__ void fma2(unsigned long long& acc, unsigned long long ab,
                                     unsigned long long w) {
    asm("fma.rn.f32x2 %0, %1, %2, %0;" : "+l"(acc) : "l"(ab), "l"(w));
}

// ---------------- dtype probe: int64 arrays have zero high-words ------------
__global__ void k_probe(const int* __restrict__ ei32) {
    if (threadIdx.x == 0 && blockIdx.x == 0) {
        int allzero = 1;
        for (int i = 1; i < 16; i += 2)
            if (ei32[i] != 0) allzero = 0;
        g_is64 = allzero;
    }
}
__device__ __forceinline__ int load_row(const int* ei32, int e, int is64) {
    return is64 ? ei32[2 * e] : ei32[e];
}
__device__ __forceinline__ int load_col(const int* ei32, int e, int is64) {
    return is64 ? ei32[2 * (N_EDGESC + e)] : ei32[N_EDGESC + e];
}

// ---------------- setup kernels ----------------
__global__ void k_zero() {
    int i = blockIdx.x * blockDim.x + threadIdx.x;
    if (i < N_NODESC) { g_deg[i] = 0.f; g_cnt[i] = 0; }
    if (i < 2 * 2 * DIM) g_stats[i] = 0.f;
}

__global__ void k_deg(const int* __restrict__ ei32, const float* __restrict__ ew) {
    int e = blockIdx.x * blockDim.x + threadIdx.x;
    if (e < N_EDGESC) {
        int is64 = g_is64;
        int c = load_col(ei32, e, is64);
        atomicAdd(&g_deg[c], ew[e]);
        atomicAdd(&g_cnt[c], 1);
    }
}

__global__ void k_scan1() {
    __shared__ int s[SCAN_B];
    int tid = threadIdx.x;
    int i = blockIdx.x * SCAN_B + tid;
    s[tid] = (i < N_NODESC) ? g_cnt[i] : 0;
    __syncthreads();
    for (int off = SCAN_B / 2; off > 0; off >>= 1) {
        if (tid < off) s[tid] += s[tid + off];
        __syncthreads();
    }
    if (tid == 0) g_bsum[blockIdx.x] = s[0];
}

__global__ void k_scan2() {
    if (threadIdx.x == 0) {
        int run = 0;
        for (int b = 0; b < NBLK; b++) { int t = g_bsum[b]; g_bsum[b] = run; run += t; }
        g_rowptr[N_NODESC] = run;
    }
}

__global__ void k_scan3() {
    __shared__ int s[SCAN_B];
    int tid = threadIdx.x;
    int i = blockIdx.x * SCAN_B + tid;
    int v = (i < N_NODESC) ? g_cnt[i] : 0;
    s[tid] = v;
    __syncthreads();
    for (int off = 1; off < SCAN_B; off <<= 1) {
        int t = (tid >= off) ? s[tid - off] : 0;
        __syncthreads();
        s[tid] += t;
        __syncthreads();
    }
    if (i < N_NODESC) {
        int excl = g_bsum[blockIdx.x] + s[tid] - v;
        g_rowptr[i] = excl;
        g_cursor[i] = excl;
    }
}

__global__ void k_edges(const int* __restrict__ ei32, const float* __restrict__ ew) {
    int e = blockIdx.x * blockDim.x + threadIdx.x;
    if (e < N_EDGESC) {
        int is64 = g_is64;
        int r = load_row(ei32, e, is64);
        int c = load_col(ei32, e, is64);
        float w = ew[e];
        float dr = g_deg[r], dc = g_deg[c];
        float nv = (dr > 0.f ? rsqrtf(dr) : 0.f) * w * (dc > 0.f ? rsqrtf(dc) : 0.f);
        int pos = atomicAdd(&g_cursor[c], 1);
        g_src[pos] = r;
        g_nrm[pos] = nv;
    }
}

// transpose both weight matrices of both layers:  WT[(ly*2+br)*D + k][j] = W[ly][j][k]
__global__ void k_transW(const float* __restrict__ Wl, const float* __restrict__ Wg) {
    int t = blockIdx.x * blockDim.x + threadIdx.x;
    if (t < 2 * 2 * DIM * DIM) {
        int j  = t & (DIM - 1);
        int k  = (t >> 7) & (DIM - 1);
        int br = (t >> 14) & 1;
        int ly = t >> 15;
        const float* src = br ? Wg : Wl;
        g_WT[t] = src[ly * DIM * DIM + j * DIM + k];
    }
}

// ---------------- GEMM: dstA = src' @ Wl^T, dstH = src' @ Wg^T -------------
// src' = src raw (fused=0) or BN+ReLU(src) with previous layer's stats (fused=1).
// Warp handles 4 rows; lane owns output cols 4l..4l+3. FFMA2 inner math.
// min 4 CTAs/SM to fix warp starvation (R12 profile: occ 36.6%, issue 29.8%).
__global__ void __launch_bounds__(256, 4) k_gemm(
    const float* __restrict__ src, int fused,
    float* __restrict__ dstA, float* __restrict__ dstH,
    const float* __restrict__ gamma, const float* __restrict__ beta, int layer) {
    __shared__ float s_sc[DIM];
    __shared__ float s_sh[DIM];
    if (fused) {
        if (threadIdx.x < DIM) {
            int d = threadIdx.x;
            const float inv_n = 1.f / (float)N_NODESC;
            float mu = g_stats[(layer - 1) * 2 * DIM + d] * inv_n;
            float var = g_stats[(layer - 1) * 2 * DIM + DIM + d] * inv_n - mu * mu;
            float sc = rsqrtf(var + BN_EPS) * gamma[(layer - 1) * DIM + d];
            s_sc[d] = sc;
            s_sh[d] = beta[(layer - 1) * DIM + d] - mu * sc;
        }
        __syncthreads();
    }
    const ulonglong2* Wl = (const ulonglong2*)(g_WT + (layer * 2 + 0) * DIM * DIM);
    const ulonglong2* Wg = (const ulonglong2*)(g_WT + (layer * 2 + 1) * DIM * DIM);
    int lane = threadIdx.x & 31;
    int warp = (blockIdx.x * blockDim.x + threadIdx.x) >> 5;
    int nwarps = (gridDim.x * blockDim.x) >> 5;

    for (int g = warp; g < NGROUPS; g += nwarps) {
        int n0 = g * ROWS_PER_WARP;
        const float4* x0 = (const float4*)(src + (size_t)n0 * DIM);
        unsigned long long al01[4], al23[4], ag01[4], ag23[4];
#pragma unroll
        for (int r = 0; r < 4; r++) {
            al01[r] = 0ULL; al23[r] = 0ULL;
            ag01[r] = 0ULL; ag23[r] = 0ULL;
        }
#pragma unroll 2
        for (int q = 0; q < 32; q++) {
            float4 xr[4];
            xr[0] = x0[q];
            xr[1] = x0[32 + q];
            xr[2] = x0[64 + q];
            xr[3] = x0[96 + q];
            if (fused) {
                float4 sc = *(const float4*)&s_sc[q * 4];
                float4 sh = *(const float4*)&s_sh[q * 4];
#pragma unroll
                for (int r = 0; r < 4; r++) {
                    xr[r].x = fmaxf(fmaf(xr[r].x, sc.x, sh.x), 0.f);
                    xr[r].y = fmaxf(fmaf(xr[r].y, sc.y, sh.y), 0.f);
                    xr[r].z = fmaxf(fmaf(xr[r].z, sc.z, sh.z), 0.f);
                    xr[r].w = fmaxf(fmaf(xr[r].w, sc.w, sh.w), 0.f);
                }
            }
#pragma unroll
            for (int kk = 0; kk < 4; kk++) {
                ulonglong2 wl = Wl[(4 * q + kk) * 32 + lane];
                ulonglong2 wg = Wg[(4 * q + kk) * 32 + lane];
#pragma unroll
                for (int r = 0; r < 4; r++) {
                    float c = (kk == 0) ? xr[r].x : (kk == 1) ? xr[r].y
                            : (kk == 2) ? xr[r].z : xr[r].w;
                    unsigned long long cc = pack_dup(c);
                    fma2(al01[r], cc, wl.x);
                    fma2(al23[r], cc, wl.y);
                    fma2(ag01[r], cc, wg.x);
                    fma2(ag23[r], cc, wg.y);
                }
            }
        }
        ulonglong2* A = (ulonglong2*)(dstA + (size_t)n0 * DIM);
        ulonglong2* H = (ulonglong2*)(dstH + (size_t)n0 * DIM);
#pragma unroll
        for (int r = 0; r < 4; r++) {
            A[r * 32 + lane] = make_ulonglong2(al01[r], al23[r]);
            H[r * 32 + lane] = make_ulonglong2(ag01[r], ag23[r]);
        }
    }
}

// ---------------- gather (CSR segment-sum) + BN stats ----------------
__global__ void __launch_bounds__(256) k_gather_bn(int layer, float* __restrict__ accbuf) {
    __shared__ float s_sum[8][DIM];
    __shared__ float s_sq[8][DIM];
    int lane = threadIdx.x & 31;
    int wib = threadIdx.x >> 5;
    int warp = (blockIdx.x * blockDim.x + threadIdx.x) >> 5;
    int nw = (gridDim.x * blockDim.x) >> 5;
    const float4* HG = (const float4*)g_hg;

    float4 sum = make_float4(0.f, 0.f, 0.f, 0.f);
    float4 sq = make_float4(0.f, 0.f, 0.f, 0.f);

    for (int n = warp; n < N_NODESC; n += nw) {
        int start = g_rowptr[n];
        int end = g_rowptr[n + 1];
        float4* A = (float4*)(accbuf + (size_t)n * DIM);
        float4 h = A[lane];
        for (int i = start; i < end; i++) {
            int r = g_src[i];
            float nv = g_nrm[i];
            float4 v = HG[r * 32 + lane];
            h.x = fmaf(nv, v.x, h.x);
            h.y = fmaf(nv, v.y, h.y);
            h.z = fmaf(nv, v.z, h.z);
            h.w = fmaf(nv, v.w, h.w);
        }
        A[lane] = h;
        sum.x += h.x; sum.y += h.y; sum.z += h.z; sum.w += h.w;
        sq.x = fmaf(h.x, h.x, sq.x);
        sq.y = fmaf(h.y, h.y, sq.y);
        sq.z = fmaf(h.z, h.z, sq.z);
        sq.w = fmaf(h.w, h.w, sq.w);
    }
    s_sum[wib][lane * 4 + 0] = sum.x;
    s_sum[wib][lane * 4 + 1] = sum.y;
    s_sum[wib][lane * 4 + 2] = sum.z;
    s_sum[wib][lane * 4 + 3] = sum.w;
    s_sq[wib][lane * 4 + 0] = sq.x;
    s_sq[wib][lane * 4 + 1] = sq.y;
    s_sq[wib][lane * 4 + 2] = sq.z;
    s_sq[wib][lane * 4 + 3] = sq.w;
    __syncthreads();
    if (threadIdx.x < DIM) {
        float ts = 0.f, tq = 0.f;
#pragma unroll
        for (int w = 0; w < 8; w++) { ts += s_sum[w][threadIdx.x]; tq += s_sq[w][threadIdx.x]; }
        atomicAdd(&g_stats[layer * 2 * DIM + threadIdx.x], ts);
        atomicAdd(&g_stats[layer * 2 * DIM + DIM + threadIdx.x], tq);
    }
}

// ---------------- BN apply (final layer, no ReLU) ----------------
__global__ void k_apply(int layer, const float* __restrict__ accbuf,
                        float* __restrict__ outp,
                        const float* __restrict__ gamma, const float* __restrict__ beta) {
    int total = N_NODESC * DIM / 4;
    const float4* A = (const float4*)accbuf;
    float4* O = (float4*)outp;
    const float inv_n = 1.f / (float)N_NODESC;
    for (int i = blockIdx.x * blockDim.x + threadIdx.x; i < total; i += gridDim.x * blockDim.x) {
        int d0 = (i & 31) * 4;
        float4 h = A[i];
        float4 s4 = *(const float4*)&g_stats[layer * 2 * DIM + d0];
        float4 q4 = *(const float4*)&g_stats[layer * 2 * DIM + DIM + d0];
        float4 ga = *(const float4*)&gamma[layer * DIM + d0];
        float4 be = *(const float4*)&beta[layer * DIM + d0];
        float4 o;
        {
            float mu = s4.x * inv_n; float var = q4.x * inv_n - mu * mu;
            o.x = (h.x - mu) * rsqrtf(var + BN_EPS) * ga.x + be.x;
        }
        {
            float mu = s4.y * inv_n; float var = q4.y * inv_n - mu * mu;
            o.y = (h.y - mu) * rsqrtf(var + BN_EPS) * ga.y + be.y;
        }
        {
            float mu = s4.z * inv_n; float var = q4.z * inv_n - mu * mu;
            o.z = (h.z - mu) * rsqrtf(var + BN_EPS) * ga.z + be.z;
        }
        {
            float mu = s4.w * inv_n; float var = q4.w * inv_n - mu * mu;
            o.w = (h.w - mu) * rsqrtf(var + BN_EPS) * ga.w + be.w;
        }
        O[i] = o;
    }
}

// ---------------- launch ----------------
extern "C" void kernel_launch(void* const* d_in, const int* in_sizes, int n_in,
                              void* d_out, int out_size) {
    const float* x = (const float*)d_in[0];
    const int* ei32 = (const int*)d_in[1];
    const float* ew = (const float*)d_in[2];
    const float* Wl = (const float*)d_in[3];
    const float* Wg = (const float*)d_in[4];
    const float* gamma = (const float*)d_in[5];
    const float* beta = (const float*)d_in[6];
    float* out = (float*)d_out;

    float* acc0; cudaGetSymbolAddress((void**)&acc0, g_acc);
    float* acc1; cudaGetSymbolAddress((void**)&acc1, g_xbuf);
    float* hgp;  cudaGetSymbolAddress((void**)&hgp, g_hg);

    // Launch order keeps gemm0 in the ncu capture slot (my index 3).
    k_probe<<<1, 32>>>(ei32);                                        // 0
    k_transW<<<(2 * 2 * DIM * DIM + 255) / 256, 256>>>(Wl, Wg);      // 1
    k_zero<<<(N_NODESC + 255) / 256, 256>>>();                       // 2
    k_gemm<<<GEMM_GRID, 256>>>(x, 0, acc0, hgp, gamma, beta, 0);     // 3  <- profiled
    k_deg<<<(N_EDGESC + 255) / 256, 256>>>(ei32, ew);                // 4
    k_scan1<<<NBLK, SCAN_B>>>();                                     // 5
    k_scan2<<<1, 32>>>();                                            // 6
    k_scan3<<<NBLK, SCAN_B>>>();                                     // 7
    k_edges<<<(N_EDGESC + 255) / 256, 256>>>(ei32, ew);              // 8

    k_gather_bn<<<592, 256>>>(0, acc0);                              // 9
    k_gemm<<<GEMM_GRID, 256>>>(acc0, 1, acc1, hgp, gamma, beta, 1);  // 10
    k_gather_bn<<<592, 256>>>(1, acc1);                              // 11
    k_apply<<<2048, 256>>>(1, acc1, out, gamma, beta);               // 12
}

// round 17
// speedup vs baseline: 1.9244x; 1.7306x over previous
#include <cuda_runtime.h>
#include <cstdint>

#define N_NODESC 100000
#define N_EDGESC 625000
#define DIM 128
#define BN_EPS 1e-5f

#define SCAN_B 512
#define NBLK ((N_NODESC + SCAN_B - 1) / SCAN_B)   // 196

#define TILE_M 64
#define NTILE ((N_NODESC + TILE_M - 1) / TILE_M)   // 1563
#define GEMM_GRID (2 * NTILE)                      // 3126 (matrix = blockIdx & 1)

// ---------------- scratch (static device globals; no allocs) ----------------
__device__ __align__(16) float g_deg[N_NODESC];
__device__ int   g_cnt[N_NODESC];
__device__ int   g_rowptr[N_NODESC + 1];
__device__ int   g_cursor[N_NODESC];
__device__ int   g_bsum[NBLK];
__device__ int   g_src[N_EDGESC];
__device__ __align__(16) float g_nrm[N_EDGESC];
__device__ __align__(16) float g_hg[N_NODESC * DIM];
__device__ __align__(16) float g_acc[N_NODESC * DIM];
__device__ __align__(16) float g_xbuf[N_NODESC * DIM];
__device__ __align__(16) float g_WT[2 * 2 * DIM * DIM];   // [layer][branch][k][j]
__device__ __align__(16) float g_stats[2 * 2 * DIM];      // [layer][sum|sumsq][d]
__device__ int g_is64;

// ---------------- packed f32x2 helpers (Blackwell sm_100+) ----------------
__device__ __forceinline__ unsigned long long pack_dup(float c) {
    unsigned long long r;
    asm("mov.b64 %0, {%1, %1};" : "=l"(r) : "f"(c));
    return r;
}
__device__ __forceinline__ void fma2(unsigned long long& acc, unsigned long long ab,
                                     unsigned long long w) {
    asm("fma.rn.f32x2 %0, %1, %2, %0;" : "+l"(acc) : "l"(ab), "l"(w));
}

// ---------------- dtype probe: int64 arrays have zero high-words ------------
__global__ void k_probe(const int* __restrict__ ei32) {
    if (threadIdx.x == 0 && blockIdx.x == 0) {
        int allzero = 1;
        for (int i = 1; i < 16; i += 2)
            if (ei32[i] != 0) allzero = 0;
        g_is64 = allzero;
    }
}
__device__ __forceinline__ int load_row(const int* ei32, int e, int is64) {
    return is64 ? ei32[2 * e] : ei32[e];
}
__device__ __forceinline__ int load_col(const int* ei32, int e, int is64) {
    return is64 ? ei32[2 * (N_EDGESC + e)] : ei32[N_EDGESC + e];
}

// ---------------- setup kernels ----------------
__global__ void k_zero() {
    int i = blockIdx.x * blockDim.x + threadIdx.x;
    if (i < N_NODESC) { g_deg[i] = 0.f; g_cnt[i] = 0; }
    if (i < 2 * 2 * DIM) g_stats[i] = 0.f;
}

__global__ void k_deg(const int* __restrict__ ei32, const float* __restrict__ ew) {
    int e = blockIdx.x * blockDim.x + threadIdx.x;
    if (e < N_EDGESC) {
        int is64 = g_is64;
        int c = load_col(ei32, e, is64);
        atomicAdd(&g_deg[c], ew[e]);
        atomicAdd(&g_cnt[c], 1);
    }
}

__global__ void k_scan1() {
    __shared__ int s[SCAN_B];
    int tid = threadIdx.x;
    int i = blockIdx.x * SCAN_B + tid;
    s[tid] = (i < N_NODESC) ? g_cnt[i] : 0;
    __syncthreads();
    for (int off = SCAN_B / 2; off > 0; off >>= 1) {
        if (tid < off) s[tid] += s[tid + off];
        __syncthreads();
    }
    if (tid == 0) g_bsum[blockIdx.x] = s[0];
}

__global__ void k_scan2() {
    if (threadIdx.x == 0) {
        int run = 0;
        for (int b = 0; b < NBLK; b++) { int t = g_bsum[b]; g_bsum[b] = run; run += t; }
        g_rowptr[N_NODESC] = run;
    }
}

__global__ void k_scan3() {
    __shared__ int s[SCAN_B];
    int tid = threadIdx.x;
    int i = blockIdx.x * SCAN_B + tid;
    int v = (i < N_NODESC) ? g_cnt[i] : 0;
    s[tid] = v;
    __syncthreads();
    for (int off = 1; off < SCAN_B; off <<= 1) {
        int t = (tid >= off) ? s[tid - off] : 0;
        __syncthreads();
        s[tid] += t;
        __syncthreads();
    }
    if (i < N_NODESC) {
        int excl = g_bsum[blockIdx.x] + s[tid] - v;
        g_rowptr[i] = excl;
        g_cursor[i] = excl;
    }
}

__global__ void k_edges(const int* __restrict__ ei32, const float* __restrict__ ew) {
    int e = blockIdx.x * blockDim.x + threadIdx.x;
    if (e < N_EDGESC) {
        int is64 = g_is64;
        int r = load_row(ei32, e, is64);
        int c = load_col(ei32, e, is64);
        float w = ew[e];
        float dr = g_deg[r], dc = g_deg[c];
        float nv = (dr > 0.f ? rsqrtf(dr) : 0.f) * w * (dc > 0.f ? rsqrtf(dc) : 0.f);
        int pos = atomicAdd(&g_cursor[c], 1);
        g_src[pos] = r;
        g_nrm[pos] = nv;
    }
}

// transpose both weight matrices of both layers:  WT[(ly*2+br)*D + k][j] = W[ly][j][k]
__global__ void k_transW(const float* __restrict__ Wl, const float* __restrict__ Wg) {
    int t = blockIdx.x * blockDim.x + threadIdx.x;
    if (t < 2 * 2 * DIM * DIM) {
        int j  = t & (DIM - 1);
        int k  = (t >> 7) & (DIM - 1);
        int br = (t >> 14) & 1;
        int ly = t >> 15;
        const float* src = br ? Wg : Wl;
        g_WT[t] = src[ly * DIM * DIM + j * DIM + k];
    }
}

// ---------------- tiled GEMM: one 64-row tile x ONE matrix per CTA ---------
// x tile staged in SMEM (BN+ReLU fused into staging when fused=1); each of the
// 8 warps computes 8 rows x 128 cols; weights from L1 (CTA-wide reuse).
__global__ void __launch_bounds__(256) k_gemm(
    const float* __restrict__ src, int fused,
    float* __restrict__ dstA, float* __restrict__ dstH,
    const float* __restrict__ gamma, const float* __restrict__ beta, int layer) {
    __shared__ __align__(16) float s_x[TILE_M * DIM];   // 32KB
    __shared__ float s_sc[DIM];
    __shared__ float s_sh[DIM];
    const int tid = threadIdx.x;
    const int mat = blockIdx.x & 1;
    const int tile = blockIdx.x >> 1;
    const int row0 = tile * TILE_M;

    if (fused) {
        if (tid < DIM) {
            int d = tid;
            const float inv_n = 1.f / (float)N_NODESC;
            float mu = g_stats[(layer - 1) * 2 * DIM + d] * inv_n;
            float var = g_stats[(layer - 1) * 2 * DIM + DIM + d] * inv_n - mu * mu;
            float sc = rsqrtf(var + BN_EPS) * gamma[(layer - 1) * DIM + d];
            s_sc[d] = sc;
            s_sh[d] = beta[(layer - 1) * DIM + d] - mu * sc;
        }
        __syncthreads();
    }

    // ---- stage x tile (coalesced float4), fused BN+ReLU optional ----
    {
        const float4* xin = (const float4*)(src + (size_t)row0 * DIM);
        float4* sx4 = (float4*)s_x;
#pragma unroll
        for (int it = 0; it < (TILE_M * DIM / 4) / 256; it++) {
            int i = it * 256 + tid;
            int r = i >> 5;                 // row within tile
            float4 v = (row0 + r < N_NODESC) ? xin[i] : make_float4(0.f, 0.f, 0.f, 0.f);
            if (fused) {
                int c0 = (i & 31) * 4;
                float4 sc = *(const float4*)&s_sc[c0];
                float4 sh = *(const float4*)&s_sh[c0];
                v.x = fmaxf(fmaf(v.x, sc.x, sh.x), 0.f);
                v.y = fmaxf(fmaf(v.y, sc.y, sh.y), 0.f);
                v.z = fmaxf(fmaf(v.z, sc.z, sh.z), 0.f);
                v.w = fmaxf(fmaf(v.w, sc.w, sh.w), 0.f);
            }
            sx4[i] = v;
        }
    }
    __syncthreads();

    const ulonglong2* W = (const ulonglong2*)(g_WT + (layer * 2 + mat) * DIM * DIM);
    float* dst = mat ? dstH : dstA;
    const int lane = tid & 31;
    const int r0 = (tid >> 5) * 8;          // warp's first row within tile

    unsigned long long a01[8], a23[8];
#pragma unroll
    for (int r = 0; r < 8; r++) { a01[r] = 0ULL; a23[r] = 0ULL; }

#pragma unroll 2
    for (int q = 0; q < 32; q++) {
        ulonglong2 w0 = W[(4 * q + 0) * 32 + lane];
        ulonglong2 w1 = W[(4 * q + 1) * 32 + lane];
        ulonglong2 w2 = W[(4 * q + 2) * 32 + lane];
        ulonglong2 w3 = W[(4 * q + 3) * 32 + lane];
#pragma unroll
        for (int r = 0; r < 8; r++) {
            float4 xv = *(const float4*)&s_x[(r0 + r) * DIM + q * 4];
            unsigned long long c0 = pack_dup(xv.x);
            unsigned long long c1 = pack_dup(xv.y);
            unsigned long long c2 = pack_dup(xv.z);
            unsigned long long c3 = pack_dup(xv.w);
            fma2(a01[r], c0, w0.x); fma2(a23[r], c0, w0.y);
            fma2(a01[r], c1, w1.x); fma2(a23[r], c1, w1.y);
            fma2(a01[r], c2, w2.x); fma2(a23[r], c2, w2.y);
            fma2(a01[r], c3, w3.x); fma2(a23[r], c3, w3.y);
        }
    }

#pragma unroll
    for (int r = 0; r < 8; r++) {
        int n = row0 + r0 + r;
        if (n < N_NODESC) {
            ulonglong2* D = (ulonglong2*)(dst + (size_t)n * DIM);
            D[lane] = make_ulonglong2(a01[r], a23[r]);
        }
    }
}

// ---------------- gather (CSR segment-sum) + BN stats ----------------
__global__ void __launch_bounds__(256) k_gather_bn(int layer, float* __restrict__ accbuf) {
    __shared__ float s_sum[8][DIM];
    __shared__ float s_sq[8][DIM];
    int lane = threadIdx.x & 31;
    int wib = threadIdx.x >> 5;
    int warp = (blockIdx.x * blockDim.x + threadIdx.x) >> 5;
    int nw = (gridDim.x * blockDim.x) >> 5;
    const float4* HG = (const float4*)g_hg;

    float4 sum = make_float4(0.f, 0.f, 0.f, 0.f);
    float4 sq = make_float4(0.f, 0.f, 0.f, 0.f);

    for (int n = warp; n < N_NODESC; n += nw) {
        int start = g_rowptr[n];
        int end = g_rowptr[n + 1];
        float4* A = (float4*)(accbuf + (size_t)n * DIM);
        float4 h = A[lane];
        for (int i = start; i < end; i++) {
            int r = g_src[i];
            float nv = g_nrm[i];
            float4 v = HG[r * 32 + lane];
            h.x = fmaf(nv, v.x, h.x);
            h.y = fmaf(nv, v.y, h.y);
            h.z = fmaf(nv, v.z, h.z);
            h.w = fmaf(nv, v.w, h.w);
        }
        A[lane] = h;
        sum.x += h.x; sum.y += h.y; sum.z += h.z; sum.w += h.w;
        sq.x = fmaf(h.x, h.x, sq.x);
        sq.y = fmaf(h.y, h.y, sq.y);
        sq.z = fmaf(h.z, h.z, sq.z);
        sq.w = fmaf(h.w, h.w, sq.w);
    }
    s_sum[wib][lane * 4 + 0] = sum.x;
    s_sum[wib][lane * 4 + 1] = sum.y;
    s_sum[wib][lane * 4 + 2] = sum.z;
    s_sum[wib][lane * 4 + 3] = sum.w;
    s_sq[wib][lane * 4 + 0] = sq.x;
    s_sq[wib][lane * 4 + 1] = sq.y;
    s_sq[wib][lane * 4 + 2] = sq.z;
    s_sq[wib][lane * 4 + 3] = sq.w;
    __syncthreads();
    if (threadIdx.x < DIM) {
        float ts = 0.f, tq = 0.f;
#pragma unroll
        for (int w = 0; w < 8; w++) { ts += s_sum[w][threadIdx.x]; tq += s_sq[w][threadIdx.x]; }
        atomicAdd(&g_stats[layer * 2 * DIM + threadIdx.x], ts);
        atomicAdd(&g_stats[layer * 2 * DIM + DIM + threadIdx.x], tq);
    }
}

// ---------------- BN apply (final layer, no ReLU) ----------------
__global__ void k_apply(int layer, const float* __restrict__ accbuf,
                        float* __restrict__ outp,
                        const float* __restrict__ gamma, const float* __restrict__ beta) {
    int total = N_NODESC * DIM / 4;
    const float4* A = (const float4*)accbuf;
    float4* O = (float4*)outp;
    const float inv_n = 1.f / (float)N_NODESC;
    for (int i = blockIdx.x * blockDim.x + threadIdx.x; i < total; i += gridDim.x * blockDim.x) {
        int d0 = (i & 31) * 4;
        float4 h = A[i];
        float4 s4 = *(const float4*)&g_stats[layer * 2 * DIM + d0];
        float4 q4 = *(const float4*)&g_stats[layer * 2 * DIM + DIM + d0];
        float4 ga = *(const float4*)&gamma[layer * DIM + d0];
        float4 be = *(const float4*)&beta[layer * DIM + d0];
        float4 o;
        {
            float mu = s4.x * inv_n; float var = q4.x * inv_n - mu * mu;
            o.x = (h.x - mu) * rsqrtf(var + BN_EPS) * ga.x + be.x;
        }
        {
            float mu = s4.y * inv_n; float var = q4.y * inv_n - mu * mu;
            o.y = (h.y - mu) * rsqrtf(var + BN_EPS) * ga.y + be.y;
        }
        {
            float mu = s4.z * inv_n; float var = q4.z * inv_n - mu * mu;
            o.z = (h.z - mu) * rsqrtf(var + BN_EPS) * ga.z + be.z;
        }
        {
            float mu = s4.w * inv_n; float var = q4.w * inv_n - mu * mu;
            o.w = (h.w - mu) * rsqrtf(var + BN_EPS) * ga.w + be.w;
        }
        O[i] = o;
    }
}

// ---------------- launch ----------------
extern "C" void kernel_launch(void* const* d_in, const int* in_sizes, int n_in,
                              void* d_out, int out_size) {
    const float* x = (const float*)d_in[0];
    const int* ei32 = (const int*)d_in[1];
    const float* ew = (const float*)d_in[2];
    const float* Wl = (const float*)d_in[3];
    const float* Wg = (const float*)d_in[4];
    const float* gamma = (const float*)d_in[5];
    const float* beta = (const float*)d_in[6];
    float* out = (float*)d_out;

    float* acc0; cudaGetSymbolAddress((void**)&acc0, g_acc);
    float* acc1; cudaGetSymbolAddress((void**)&acc1, g_xbuf);
    float* hgp;  cudaGetSymbolAddress((void**)&hgp, g_hg);

    // Launch order keeps gemm0 in the ncu capture slot (my index 3).
    k_probe<<<1, 32>>>(ei32);                                        // 0
    k_transW<<<(2 * 2 * DIM * DIM + 255) / 256, 256>>>(Wl, Wg);      // 1
    k_zero<<<(N_NODESC + 255) / 256, 256>>>();                       // 2
    k_gemm<<<GEMM_GRID, 256>>>(x, 0, acc0, hgp, gamma, beta, 0);     // 3  <- profiled
    k_deg<<<(N_EDGESC + 255) / 256, 256>>>(ei32, ew);                // 4
    k_scan1<<<NBLK, SCAN_B>>>();                                     // 5
    k_scan2<<<1, 32>>>();                                            // 6
    k_scan3<<<NBLK, SCAN_B>>>();                                     // 7
    k_edges<<<(N_EDGESC + 255) / 256, 256>>>(ei32, ew);              // 8

    k_gather_bn<<<592, 256>>>(0, acc0);                              // 9
    k_gemm<<<GEMM_GRID, 256>>>(acc0, 1, acc1, hgp, gamma, beta, 1);  // 10
    k_gather_bn<<<592, 256>>>(1, acc1);                              // 11
    k_apply<<<2048, 256>>>(1, acc1, out, gamma, beta);               // 12
}